// round 1
// baseline (speedup 1.0000x reference)
#include <cuda_runtime.h>
#include <cuda_bf16.h>
#include <math.h>

// Problem constants (fixed by the reference):
//   feat_rgb: [B=4, C=256, IH=128, IW=512] fp32
//   rot, shift_u, shift_v: [4] fp32 ; meter_per_pixel: [1] fp32
//   out: [4, 256, BEV_H=128, BEV_W=512] fp32
#define BEV_H 128
#define BEV_W 512
#define IH    128
#define IW    512
#define NB    4
#define NC    256
#define PLANE (IH * IW)            // 65536
#define CHUNK 64                   // channels per thread
#define NCH   (NC / CHUNK)         // 4 chunks

#define TWO_PI_F   6.2831853071795864769f
#define PI_F       3.1415926535897932385f
#define HALF_PI_F  1.5707963267948966192f

__device__ __forceinline__ float mod2pi(float x) {
    // matches jnp.mod for f32: lax.rem (== fmodf, exact) then sign-adjust
    float m = fmodf(x, TWO_PI_F);
    if (m < 0.0f) m += TWO_PI_F;
    return m;
}

__global__ void __launch_bounds__(256)
bev_project_kernel(const float* __restrict__ feat,
                   const float* __restrict__ rot,
                   const float* __restrict__ shift_u,
                   const float* __restrict__ shift_v,
                   const float* __restrict__ mpp,
                   float* __restrict__ out)
{
    int t = blockIdx.x * blockDim.x + threadIdx.x;
    // t layout: [b][chunk][i][j], j fastest (coalesced stores & gathers)
    int j  = t & (BEV_W - 1);
    int i  = (t >> 9) & (BEV_H - 1);
    int cc = (t >> 16) & (NCH - 1);
    int b  = t >> 18;
    if (b >= NB) return;

    const float r  = rot[b];
    const float su = shift_u[b];
    const float sv = shift_v[b];
    const float m  = mpp[0];

    // --- coordinate computation (once per spatial position) ---
    float center_v = (float)BEV_H * 0.5f - 0.5f + sv;   // 63.5 + sv
    float center_u = (float)BEV_W * 0.5f - 0.5f + su;   // 255.5 + su
    float dy = (float)i - center_v;
    float dx = (float)j - center_u;
    float radius = sqrtf(dy * dy + dx * dx);

    float theta = atan2f(dy, dx);
    theta = mod2pi(-HALF_PI_F + mod2pi(theta));
    theta = mod2pi(theta + r * TWO_PI_F);               // rot*360/180*pi == rot*2pi
    float u = theta / TWO_PI_F * (float)IW;

    float dist = radius * m;
    float phi  = atan2f(dist, -2.0f);                   // GRD_HEIGHT = -2.0
    float v    = phi / PI_F * (float)IH;

    // --- bilinear corners & weights (clamped-corner weights, per reference) ---
    float fx = floorf(u);
    float fy = floorf(v);
    float x0 = fminf(fmaxf(fx,        0.0f), (float)(IW - 1));
    float x1 = fminf(fmaxf(fx + 1.0f, 0.0f), (float)(IW - 1));
    float y0 = fminf(fmaxf(fy,        0.0f), (float)(IH - 1));
    float y1 = fminf(fmaxf(fy + 1.0f, 0.0f), (float)(IH - 1));

    float w_nw = (x1 - u) * (y1 - v);
    float w_ne = (u - x0) * (y1 - v);
    float w_sw = (x1 - u) * (v - y0);
    float w_se = (u - x0) * (v - y0);

    int ix0 = (int)x0, ix1 = (int)x1, iy0 = (int)y0, iy1 = (int)y1;
    int i00 = iy0 * IW + ix0;
    int i01 = iy0 * IW + ix1;
    int i10 = iy1 * IW + ix0;
    int i11 = iy1 * IW + ix1;

    // --- channel loop: 4 gathers + 1 store per channel ---
    int c0 = cc * CHUNK;
    const float* __restrict__ p = feat + (size_t)(b * NC + c0) * PLANE;
    float* __restrict__ o = out + (size_t)((b * NC + c0) * BEV_H + i) * BEV_W + j;

    #pragma unroll 4
    for (int c = 0; c < CHUNK; ++c) {
        float a00 = __ldg(p + i00);
        float a01 = __ldg(p + i01);
        float a10 = __ldg(p + i10);
        float a11 = __ldg(p + i11);
        *o = a00 * w_nw + a01 * w_ne + a10 * w_sw + a11 * w_se;
        p += PLANE;
        o += (size_t)BEV_H * BEV_W;
    }
}

extern "C" void kernel_launch(void* const* d_in, const int* in_sizes, int n_in,
                              void* d_out, int out_size)
{
    const float* feat    = (const float*)d_in[0];
    const float* rot     = (const float*)d_in[1];
    const float* shift_u = (const float*)d_in[2];
    const float* shift_v = (const float*)d_in[3];
    const float* mpp     = (const float*)d_in[4];
    float* out = (float*)d_out;

    int total = NB * NCH * BEV_H * BEV_W;   // 1,048,576 threads
    int threads = 256;
    int blocks = (total + threads - 1) / threads;
    bev_project_kernel<<<blocks, threads>>>(feat, rot, shift_u, shift_v, mpp, out);
}